// round 10
// baseline (speedup 1.0000x reference)
#include <cuda_runtime.h>
#include <math.h>
#include <stdint.h>

#define BB 2
#define NN 160
#define HH 256
#define C3 768
#define FF 512
#define NP (NN*NN)            // 25600
#define MM (BB*NN)            // 320
#define LOGIT_ELEMS (BB*NP*2) // 102400 per head
#define EMB_OFF (3*LOGIT_ELEMS)

// PQ scratch: [h = t*2+s][m][f]
__device__ float g_PQ[3 * 2 * MM * FF];

#define FFMA2(acc, a, b) asm("fma.rn.f32x2 %0, %1, %2, %0;" : "+l"(acc) : "l"(a), "l"(b))
#define PACKDUP(d, x)    asm("mov.b64 %0, {%1, %1};" : "=l"(d) : "r"(__float_as_uint(x)))
#define UNPK(lo, hi, v)  asm("mov.b64 {%0, %1}, %2;" : "=r"(lo), "=r"(hi) : "l"(v))

#define BM 32
#define BN 64
#define BK 16
#define NK 48
#define AST 36               // 32 rows + pad
#define GEMM_BLOCKS 480      // 10 mt * 48
#define JT 10
#define WRA_BLOCKS 2400
#define WRB_BLOCKS 2720
#define LG_BLOCKS 150

// smem union: gemm As 2*16*36*4=4608 + Bs 2*16*64*4=8192 = 12800
//             logits 16896+16384+512 = 33792 ; writer 11*3072+8 = 33800
#define SMEM_BYTES 33824

// ---------------- writer role: TMA bulk pipeline ----------------
// wb in [0, 5120): b = wb/2560, i = (wb%2560)/16, j0 = ((wb%2560)%16)*10
__device__ __forceinline__ void writer_role(
    int wb,
    const float* __restrict__ geo, const float* __restrict__ app, const float* __restrict__ con,
    float* __restrict__ out, int tid, char* sm)
{
    const int b  = wb / 2560;
    const int rem = wb % 2560;
    const int i  = rem / 16;
    const int j0 = (rem % 16) * JT;

    const uint32_t sbase = (uint32_t)__cvta_generic_to_shared(sm);
    const uint32_t mbar  = sbase + 11 * 3072;

    if (tid == 0) {
        asm volatile("mbarrier.init.shared.b64 [%0], 1;" :: "r"(mbar) : "memory");
    }
    __syncthreads();
    if (tid == 0) {
        asm volatile("mbarrier.arrive.expect_tx.shared.b64 _, [%0], %1;"
                     :: "r"(mbar), "r"(11u * 3072u) : "memory");
    }
    __syncthreads();

    if (tid < 33) {
        const int r = tid / 3, seg = tid - 3 * (tid / 3);
        const int n = (r < JT) ? (j0 + r) : i;
        const float* src = ((seg == 0) ? geo : (seg == 1) ? app : con)
                           + ((size_t)b * NN + n) * HH;
        asm volatile(
            "cp.async.bulk.shared::cluster.global.mbarrier::complete_tx::bytes "
            "[%0], [%1], %2, [%3];"
            :: "r"(sbase + (uint32_t)(r * 3072 + seg * 1024)), "l"(src),
               "r"(1024u), "r"(mbar) : "memory");
    }

    if (tid < 2 * JT) {
        asm volatile(
            "{\n\t.reg .pred P;\n"
            "W%=:\n\t"
            "mbarrier.try_wait.parity.shared.b64 P, [%0], 0, 0x989680;\n\t"
            "@!P bra W%=;\n\t}"
            :: "r"(mbar) : "memory");

        const int jj = tid >> 1, half = tid & 1;
        const size_t pidx = (size_t)b * NP + (size_t)i * NN + (j0 + jj);
        float* dst = out + EMB_OFF + pidx * 1536 + half * 768;
        const uint32_t src = sbase + (uint32_t)((half ? JT : jj) * 3072);
        asm volatile(
            "cp.async.bulk.global.shared::cta.bulk_group [%0], [%1], %2;"
            :: "l"(dst), "r"(src), "r"(3072u) : "memory");
        asm volatile("cp.async.bulk.commit_group;" ::: "memory");
        asm volatile("cp.async.bulk.wait_group 0;" ::: "memory");
    }
    __syncthreads();
}

// ---------------- Kernel 1: GEMM (BM=32) + writer half A ----------------
__global__ __launch_bounds__(256) void k1_gemm_wr(
    const float* __restrict__ geo, const float* __restrict__ app, const float* __restrict__ con,
    const float* __restrict__ W1c, const float* __restrict__ b1c,
    const float* __restrict__ W1r, const float* __restrict__ b1r,
    const float* __restrict__ W1l, const float* __restrict__ b1l,
    float* __restrict__ out)
{
    __shared__ __align__(128) char sm[SMEM_BYTES];
    const int g = blockIdx.x;
    const int tid = threadIdx.x;

    if (g < GEMM_BLOCKS) {
        float (*As)[BK*AST] = (float(*)[BK*AST])sm;
        float (*Bs)[BK*BN]  = (float(*)[BK*BN])(sm + 2*BK*AST*4);
        const int nt = g % 48;
        const int mt = g / 48;           // 0..9
        const int t  = nt >> 4;
        const int s  = (nt >> 3) & 1;
        const int f0 = (nt & 7) * BN;
        const float* W1 = (t==0 ? W1c : (t==1 ? W1r : W1l)) + (size_t)s * C3 * FF;
        const float* b1 = (t==0 ? b1c : (t==1 ? b1r : b1l));
        const int m0 = mt * BM;

        const int arow = (tid & 127) >> 2, av = tid & 3;  // A load (tid<128)
        const int kr = tid >> 4, fo = (tid & 15) * 4;     // B load
        const int rg = tid >> 4, cg = tid & 15;           // compute: 2m x 4n

        unsigned long long acc2[2][2];
        acc2[0][0] = acc2[0][1] = acc2[1][0] = acc2[1][1] = 0ull;

        float4 pa = make_float4(0,0,0,0), pb;
        if (tid < 128)
            pa = *(const float4*)(geo + (size_t)(m0 + arow) * HH + av * 4);
        pb = *(const float4*)(W1 + (size_t)kr * FF + f0 + fo);
        if (tid < 128) {
            As[0][(av*4+0)*AST + arow] = pa.x;
            As[0][(av*4+1)*AST + arow] = pa.y;
            As[0][(av*4+2)*AST + arow] = pa.z;
            As[0][(av*4+3)*AST + arow] = pa.w;
        }
        *(float4*)&Bs[0][kr*BN + fo] = pb;
        __syncthreads();

        for (int kt = 0; kt < NK; kt++) {
            const int cur = kt & 1;
            const int nxt = cur ^ 1;
            if (kt + 1 < NK) {
                const int c0 = (kt + 1) * BK;
                const float* segp = (c0 < 256) ? geo : ((c0 < 512) ? app : con);
                if (tid < 128)
                    pa = *(const float4*)(segp + (size_t)(m0 + arow) * HH + (c0 & 255) + av * 4);
                pb = *(const float4*)(W1 + (size_t)(c0 + kr) * FF + f0 + fo);
            }
            #pragma unroll
            for (int k = 0; k < BK; k++) {
                const float2 a2 = *(const float2*)&As[cur][k*AST + rg*2];
                const ulonglong2 b2v = *(const ulonglong2*)&Bs[cur][k*BN + cg*4];
                unsigned long long a0, a1;
                PACKDUP(a0, a2.x);
                PACKDUP(a1, a2.y);
                FFMA2(acc2[0][0], a0, b2v.x);
                FFMA2(acc2[0][1], a0, b2v.y);
                FFMA2(acc2[1][0], a1, b2v.x);
                FFMA2(acc2[1][1], a1, b2v.y);
            }
            if (kt + 1 < NK) {
                __syncthreads();
                if (tid < 128) {
                    As[nxt][(av*4+0)*AST + arow] = pa.x;
                    As[nxt][(av*4+1)*AST + arow] = pa.y;
                    As[nxt][(av*4+2)*AST + arow] = pa.z;
                    As[nxt][(av*4+3)*AST + arow] = pa.w;
                }
                *(float4*)&Bs[nxt][kr*BN + fo] = pb;
                __syncthreads();
            }
        }

        float bv[4] = {0.f, 0.f, 0.f, 0.f};
        if (s == 1) {
            const float4 tb = *(const float4*)(b1 + f0 + cg*4);
            bv[0]=tb.x; bv[1]=tb.y; bv[2]=tb.z; bv[3]=tb.w;
        }
        const size_t hb = (size_t)(t*2 + s) * MM * FF;
        #pragma unroll
        for (int a = 0; a < 2; a++) {
            const int m = m0 + rg*2 + a;
            unsigned int lo0, hi0, lo1, hi1;
            UNPK(lo0, hi0, acc2[a][0]);
            UNPK(lo1, hi1, acc2[a][1]);
            *(float4*)(g_PQ + hb + (size_t)m * FF + f0 + cg*4) =
                make_float4(__uint_as_float(lo0) + bv[0], __uint_as_float(hi0) + bv[1],
                            __uint_as_float(lo1) + bv[2], __uint_as_float(hi1) + bv[3]);
        }
    } else {
        writer_role(g - GEMM_BLOCKS, geo, app, con, out, tid, sm);
    }
}

// ---------------- Kernel 2: logits (32i x 32j, acc[4]) + writer half B ----------------
__global__ __launch_bounds__(256) void k2_lg_wr(
    const float* __restrict__ geo, const float* __restrict__ app, const float* __restrict__ con,
    float* __restrict__ out,
    const float* __restrict__ W2c, const float* __restrict__ b2c,
    const float* __restrict__ W2r, const float* __restrict__ b2r,
    const float* __restrict__ W2l, const float* __restrict__ b2l)
{
    __shared__ __align__(128) char sm[SMEM_BYTES];
    const int g = blockIdx.x;
    const int tid = threadIdx.x;

    if (g < LG_BLOCKS) {
        float* sP = (float*)sm;            // 32*132
        float* sQ = sP + 32*132;           // 32*128
        float* sW = sQ + 32*128;           // 128
        const int t = g / 50;
        const int r50 = g % 50;
        const int b = r50 / 25;
        const int r25 = r50 % 25;
        const int i0 = (r25 / 5) * 32;
        const int j0 = (r25 % 5) * 32;
        const float* W2 = (t==0 ? W2c : (t==1 ? W2r : W2l));
        const float* b2 = (t==0 ? b2c : (t==1 ? b2r : b2l));
        const size_t boff = (size_t)b * NN * FF;
        const float* Pb = g_PQ + (size_t)(t*2 + 0) * MM * FF + boff;
        const float* Qb = g_PQ + (size_t)(t*2 + 1) * MM * FF + boff;
        const int il = tid >> 5, jl = tid & 31;
        const int lr = tid >> 3, lv = tid & 7;

        float acc[4] = {0.f, 0.f, 0.f, 0.f};
        for (int fc = 0; fc < 4; fc++) {
            const int f0 = fc * 128;
            {
                const size_t ro = (size_t)(j0 + lr) * FF + f0;
                float* dp = sP + lr * 132;
                #pragma unroll
                for (int u = 0; u < 4; u++) {
                    const int fl = (lv + u * 8) * 4;
                    *(float4*)(dp + fl) = *(const float4*)(Pb + ro + fl);
                }
            }
            {
                const size_t ro = (size_t)(i0 + lr) * FF + f0;
                float* dp = sQ + lr * 128;
                #pragma unroll
                for (int u = 0; u < 4; u++) {
                    const int fl = (lv + u * 8) * 4;
                    *(float4*)(dp + fl) = *(const float4*)(Qb + ro + fl);
                }
            }
            if (tid < 128) {
                const float2 w2v = ((const float2*)W2)[f0 + tid];
                sW[tid] = w2v.x - w2v.y;
            }
            __syncthreads();

            const float* pr = sP + jl * 132;
            const float* q0 = sQ + (il * 4) * 128;
            #pragma unroll 4
            for (int f = 0; f < 128; f += 4) {
                const float4 p = *(const float4*)(pr + f);
                const float4 w = *(const float4*)(sW + f);
                #pragma unroll
                for (int a = 0; a < 4; a++) {
                    const float4 q = *(const float4*)(q0 + a * 128 + f);
                    acc[a] = fmaf(fmaxf(p.x + q.x, 0.f), w.x, acc[a]);
                    acc[a] = fmaf(fmaxf(p.y + q.y, 0.f), w.y, acc[a]);
                    acc[a] = fmaf(fmaxf(p.z + q.z, 0.f), w.z, acc[a]);
                    acc[a] = fmaf(fmaxf(p.w + q.w, 0.f), w.w, acc[a]);
                }
            }
            __syncthreads();
        }

        const float bd = b2[0] - b2[1];
        float2* o = (float2*)(out + (size_t)t * LOGIT_ELEMS) + (size_t)b * NP;
        const int j = j0 + jl;
        #pragma unroll
        for (int a = 0; a < 4; a++) {
            const float d = acc[a] + bd;
            const float p0 = 1.0f / (1.0f + __expf(-d));
            o[(size_t)(i0 + il*4 + a) * NN + j] = make_float2(p0, 1.0f - p0);
        }
    } else {
        writer_role(WRA_BLOCKS + (g - LG_BLOCKS), geo, app, con, out, tid, sm);
    }
}

extern "C" void kernel_launch(void* const* d_in, const int* in_sizes, int n_in,
                              void* d_out, int out_size) {
    const float* geo = (const float*)d_in[0];
    const float* app = (const float*)d_in[1];
    const float* con = (const float*)d_in[2];
    const float* W1c = (const float*)d_in[3];
    const float* b1c = (const float*)d_in[4];
    const float* W2c = (const float*)d_in[5];
    const float* b2c = (const float*)d_in[6];
    const float* W1r = (const float*)d_in[7];
    const float* b1r = (const float*)d_in[8];
    const float* W2r = (const float*)d_in[9];
    const float* b2r = (const float*)d_in[10];
    const float* W1l = (const float*)d_in[11];
    const float* b1l = (const float*)d_in[12];
    const float* W2l = (const float*)d_in[13];
    const float* b2l = (const float*)d_in[14];
    float* out = (float*)d_out;

    k1_gemm_wr<<<GEMM_BLOCKS + WRA_BLOCKS, 256>>>(geo, app, con,
                                                  W1c, b1c, W1r, b1r, W1l, b1l, out);
    k2_lg_wr<<<LG_BLOCKS + WRB_BLOCKS, 256>>>(geo, app, con, out,
                                              W2c, b2c, W2r, b2r, W2l, b2l);
}

// round 11
// speedup vs baseline: 1.1565x; 1.1565x over previous
#include <cuda_runtime.h>
#include <math.h>
#include <stdint.h>

#define BB 2
#define NN 160
#define HH 256
#define C3 768
#define FF 512
#define NP (NN*NN)            // 25600
#define MM (BB*NN)            // 320
#define LOGIT_ELEMS (BB*NP*2) // 102400 per head
#define EMB_OFF (3*LOGIT_ELEMS)

// PQ scratch: [h = t*2+s][m][f]
__device__ float g_PQ[3 * 2 * MM * FF];

#define FFMA2(acc, a, b) asm("fma.rn.f32x2 %0, %1, %2, %0;" : "+l"(acc) : "l"(a), "l"(b))
#define PACKDUP(d, x)    asm("mov.b64 %0, {%1, %1};" : "=l"(d) : "r"(__float_as_uint(x)))
#define UNPK(lo, hi, v)  asm("mov.b64 {%0, %1}, %2;" : "=r"(lo), "=r"(hi) : "l"(v))

#define BM 64
#define BN 64
#define BK 16
#define NK 48
#define AST 68
#define GEMM_BLOCKS 240
#define JT 10
#define WRA_BLOCKS 2560
#define WRB_BLOCKS 2560
#define LG_BLOCKS 150

#define SMEM_BYTES 33824   // writer 33800 / logits 33792 union

// ---------------- writer role: TMA bulk pipeline ----------------
// wb in [0, 5120): b = wb/2560, i = (wb%2560)/16, j0 = ((wb%2560)%16)*10
__device__ __forceinline__ void writer_role(
    int wb,
    const float* __restrict__ geo, const float* __restrict__ app, const float* __restrict__ con,
    float* __restrict__ out, int tid, char* sm)
{
    const int b  = wb / 2560;
    const int rem = wb % 2560;
    const int i  = rem / 16;
    const int j0 = (rem % 16) * JT;

    const uint32_t sbase = (uint32_t)__cvta_generic_to_shared(sm);
    const uint32_t mbar  = sbase + 11 * 3072;

    if (tid == 0) {
        asm volatile("mbarrier.init.shared.b64 [%0], 1;" :: "r"(mbar) : "memory");
    }
    __syncthreads();
    if (tid == 0) {
        asm volatile("mbarrier.arrive.expect_tx.shared.b64 _, [%0], %1;"
                     :: "r"(mbar), "r"(11u * 3072u) : "memory");
    }
    __syncthreads();

    if (tid < 33) {
        const int r = tid / 3, seg = tid - 3 * (tid / 3);
        const int n = (r < JT) ? (j0 + r) : i;
        const float* src = ((seg == 0) ? geo : (seg == 1) ? app : con)
                           + ((size_t)b * NN + n) * HH;
        asm volatile(
            "cp.async.bulk.shared::cluster.global.mbarrier::complete_tx::bytes "
            "[%0], [%1], %2, [%3];"
            :: "r"(sbase + (uint32_t)(r * 3072 + seg * 1024)), "l"(src),
               "r"(1024u), "r"(mbar) : "memory");
    }

    if (tid < 2 * JT) {
        asm volatile(
            "{\n\t.reg .pred P;\n"
            "W%=:\n\t"
            "mbarrier.try_wait.parity.shared.b64 P, [%0], 0, 0x989680;\n\t"
            "@!P bra W%=;\n\t}"
            :: "r"(mbar) : "memory");

        const int jj = tid >> 1, half = tid & 1;
        const size_t pidx = (size_t)b * NP + (size_t)i * NN + (j0 + jj);
        float* dst = out + EMB_OFF + pidx * 1536 + half * 768;
        const uint32_t src = sbase + (uint32_t)((half ? JT : jj) * 3072);
        asm volatile(
            "cp.async.bulk.global.shared::cta.bulk_group [%0], [%1], %2;"
            :: "l"(dst), "r"(src), "r"(3072u) : "memory");
        asm volatile("cp.async.bulk.commit_group;" ::: "memory");
        asm volatile("cp.async.bulk.wait_group 0;" ::: "memory");
    }
    __syncthreads();
}

// ---------------- GEMM kernel (side stream): PQ = emb @ W1 halves ----------------
__global__ __launch_bounds__(256) void k_gemm(
    const float* __restrict__ geo, const float* __restrict__ app, const float* __restrict__ con,
    const float* __restrict__ W1c, const float* __restrict__ b1c,
    const float* __restrict__ W1r, const float* __restrict__ b1r,
    const float* __restrict__ W1l, const float* __restrict__ b1l)
{
    __shared__ float As[2][BK*AST];
    __shared__ float Bs[2][BK*BN];
    const int g = blockIdx.x;
    const int tid = threadIdx.x;

    const int nt = g % 48;
    const int mt = g / 48;
    const int t  = nt >> 4;
    const int s  = (nt >> 3) & 1;
    const int f0 = (nt & 7) * BN;
    const float* W1 = (t==0 ? W1c : (t==1 ? W1r : W1l)) + (size_t)s * C3 * FF;
    const float* b1 = (t==0 ? b1c : (t==1 ? b1r : b1l));
    const int m0 = mt * BM;

    const int arow = tid >> 2, av = tid & 3;
    const int kr = tid >> 4, fo = (tid & 15) * 4;
    const int rg = tid >> 4, cg = tid & 15;

    unsigned long long acc2[4][2];
    #pragma unroll
    for (int a = 0; a < 4; a++) { acc2[a][0] = 0ull; acc2[a][1] = 0ull; }

    float4 pa, pb;
    pa = *(const float4*)(geo + (size_t)(m0 + arow) * HH + av * 4);
    pb = *(const float4*)(W1 + (size_t)kr * FF + f0 + fo);
    As[0][(av*4+0)*AST + arow] = pa.x;
    As[0][(av*4+1)*AST + arow] = pa.y;
    As[0][(av*4+2)*AST + arow] = pa.z;
    As[0][(av*4+3)*AST + arow] = pa.w;
    *(float4*)&Bs[0][kr*BN + fo] = pb;
    __syncthreads();

    for (int kt = 0; kt < NK; kt++) {
        const int cur = kt & 1;
        const int nxt = cur ^ 1;
        if (kt + 1 < NK) {
            const int c0 = (kt + 1) * BK;
            const float* segp = (c0 < 256) ? geo : ((c0 < 512) ? app : con);
            pa = *(const float4*)(segp + (size_t)(m0 + arow) * HH + (c0 & 255) + av * 4);
            pb = *(const float4*)(W1 + (size_t)(c0 + kr) * FF + f0 + fo);
        }
        #pragma unroll
        for (int k = 0; k < BK; k++) {
            const float4 a4 = *(const float4*)&As[cur][k*AST + rg*4];
            const ulonglong2 b2v = *(const ulonglong2*)&Bs[cur][k*BN + cg*4];
            float avv[4] = {a4.x, a4.y, a4.z, a4.w};
            #pragma unroll
            for (int a = 0; a < 4; a++) {
                unsigned long long ad;
                PACKDUP(ad, avv[a]);
                FFMA2(acc2[a][0], ad, b2v.x);
                FFMA2(acc2[a][1], ad, b2v.y);
            }
        }
        if (kt + 1 < NK) {
            __syncthreads();
            As[nxt][(av*4+0)*AST + arow] = pa.x;
            As[nxt][(av*4+1)*AST + arow] = pa.y;
            As[nxt][(av*4+2)*AST + arow] = pa.z;
            As[nxt][(av*4+3)*AST + arow] = pa.w;
            *(float4*)&Bs[nxt][kr*BN + fo] = pb;
            __syncthreads();
        }
    }

    float bv[4] = {0.f, 0.f, 0.f, 0.f};
    if (s == 1) {
        const float4 tb = *(const float4*)(b1 + f0 + cg*4);
        bv[0]=tb.x; bv[1]=tb.y; bv[2]=tb.z; bv[3]=tb.w;
    }
    const size_t hb = (size_t)(t*2 + s) * MM * FF;
    #pragma unroll
    for (int a = 0; a < 4; a++) {
        const int m = m0 + rg*4 + a;
        unsigned int lo0, hi0, lo1, hi1;
        UNPK(lo0, hi0, acc2[a][0]);
        UNPK(lo1, hi1, acc2[a][1]);
        *(float4*)(g_PQ + hb + (size_t)m * FF + f0 + cg*4) =
            make_float4(__uint_as_float(lo0) + bv[0], __uint_as_float(hi0) + bv[1],
                        __uint_as_float(lo1) + bv[2], __uint_as_float(hi1) + bv[3]);
    }
}

// ---------------- Kernel 1: pure writer (half A) ----------------
__global__ __launch_bounds__(256) void k1_wr(
    const float* __restrict__ geo, const float* __restrict__ app, const float* __restrict__ con,
    float* __restrict__ out)
{
    __shared__ __align__(128) char sm[SMEM_BYTES];
    writer_role(blockIdx.x, geo, app, con, out, threadIdx.x, sm);
}

// ---------------- Kernel 2: logits (32i x 32j, acc[4]) + writer half B ----------------
__global__ __launch_bounds__(256) void k2_lg_wr(
    const float* __restrict__ geo, const float* __restrict__ app, const float* __restrict__ con,
    float* __restrict__ out,
    const float* __restrict__ W2c, const float* __restrict__ b2c,
    const float* __restrict__ W2r, const float* __restrict__ b2r,
    const float* __restrict__ W2l, const float* __restrict__ b2l)
{
    __shared__ __align__(128) char sm[SMEM_BYTES];
    const int g = blockIdx.x;
    const int tid = threadIdx.x;

    if (g < LG_BLOCKS) {
        float* sP = (float*)sm;            // 32*132
        float* sQ = sP + 32*132;           // 32*128
        float* sW = sQ + 32*128;           // 128
        const int t = g / 50;
        const int r50 = g % 50;
        const int b = r50 / 25;
        const int r25 = r50 % 25;
        const int i0 = (r25 / 5) * 32;
        const int j0 = (r25 % 5) * 32;
        const float* W2 = (t==0 ? W2c : (t==1 ? W2r : W2l));
        const float* b2 = (t==0 ? b2c : (t==1 ? b2r : b2l));
        const size_t boff = (size_t)b * NN * FF;
        const float* Pb = g_PQ + (size_t)(t*2 + 0) * MM * FF + boff;
        const float* Qb = g_PQ + (size_t)(t*2 + 1) * MM * FF + boff;
        const int il = tid >> 5, jl = tid & 31;
        const int lr = tid >> 3, lv = tid & 7;

        float acc[4] = {0.f, 0.f, 0.f, 0.f};
        for (int fc = 0; fc < 4; fc++) {
            const int f0 = fc * 128;
            {
                const size_t ro = (size_t)(j0 + lr) * FF + f0;
                float* dp = sP + lr * 132;
                #pragma unroll
                for (int u = 0; u < 4; u++) {
                    const int fl = (lv + u * 8) * 4;
                    *(float4*)(dp + fl) = *(const float4*)(Pb + ro + fl);
                }
            }
            {
                const size_t ro = (size_t)(i0 + lr) * FF + f0;
                float* dp = sQ + lr * 128;
                #pragma unroll
                for (int u = 0; u < 4; u++) {
                    const int fl = (lv + u * 8) * 4;
                    *(float4*)(dp + fl) = *(const float4*)(Qb + ro + fl);
                }
            }
            if (tid < 128) {
                const float2 w2v = ((const float2*)W2)[f0 + tid];
                sW[tid] = w2v.x - w2v.y;
            }
            __syncthreads();

            const float* pr = sP + jl * 132;
            const float* q0 = sQ + (il * 4) * 128;
            #pragma unroll 4
            for (int f = 0; f < 128; f += 4) {
                const float4 p = *(const float4*)(pr + f);
                const float4 w = *(const float4*)(sW + f);
                #pragma unroll
                for (int a = 0; a < 4; a++) {
                    const float4 q = *(const float4*)(q0 + a * 128 + f);
                    acc[a] = fmaf(fmaxf(p.x + q.x, 0.f), w.x, acc[a]);
                    acc[a] = fmaf(fmaxf(p.y + q.y, 0.f), w.y, acc[a]);
                    acc[a] = fmaf(fmaxf(p.z + q.z, 0.f), w.z, acc[a]);
                    acc[a] = fmaf(fmaxf(p.w + q.w, 0.f), w.w, acc[a]);
                }
            }
            __syncthreads();
        }

        const float bd = b2[0] - b2[1];
        float2* o = (float2*)(out + (size_t)t * LOGIT_ELEMS) + (size_t)b * NP;
        const int j = j0 + jl;
        #pragma unroll
        for (int a = 0; a < 4; a++) {
            const float d = acc[a] + bd;
            const float p0 = 1.0f / (1.0f + __expf(-d));
            o[(size_t)(i0 + il*4 + a) * NN + j] = make_float2(p0, 1.0f - p0);
        }
    } else {
        writer_role(WRA_BLOCKS + (g - LG_BLOCKS), geo, app, con, out, tid, sm);
    }
}

extern "C" void kernel_launch(void* const* d_in, const int* in_sizes, int n_in,
                              void* d_out, int out_size) {
    const float* geo = (const float*)d_in[0];
    const float* app = (const float*)d_in[1];
    const float* con = (const float*)d_in[2];
    const float* W1c = (const float*)d_in[3];
    const float* b1c = (const float*)d_in[4];
    const float* W2c = (const float*)d_in[5];
    const float* b2c = (const float*)d_in[6];
    const float* W1r = (const float*)d_in[7];
    const float* b1r = (const float*)d_in[8];
    const float* W2r = (const float*)d_in[9];
    const float* b2r = (const float*)d_in[10];
    const float* W1l = (const float*)d_in[11];
    const float* b1l = (const float*)d_in[12];
    const float* W2l = (const float*)d_in[13];
    const float* b2l = (const float*)d_in[14];
    float* out = (float*)d_out;

    // One-time creation on the first (non-captured) correctness call; the
    // captured calls only record/wait/launch — identical GPU work every call.
    static cudaStream_t s2 = nullptr;
    static cudaEvent_t evF = nullptr, evJ = nullptr;
    if (s2 == nullptr) {
        cudaStreamCreateWithFlags(&s2, cudaStreamNonBlocking);
        cudaEventCreateWithFlags(&evF, cudaEventDisableTiming);
        cudaEventCreateWithFlags(&evJ, cudaEventDisableTiming);
    }

    // fork: GEMM on side stream, concurrent with the k1 writer
    cudaEventRecord(evF, 0);
    cudaStreamWaitEvent(s2, evF, 0);
    k_gemm<<<GEMM_BLOCKS, 256, 0, s2>>>(geo, app, con,
                                        W1c, b1c, W1r, b1r, W1l, b1l);
    cudaEventRecord(evJ, s2);

    k1_wr<<<WRA_BLOCKS, 256>>>(geo, app, con, out);

    // join: k2 (logits) needs PQ from the GEMM
    cudaStreamWaitEvent(0, evJ, 0);
    k2_lg_wr<<<LG_BLOCKS + WRB_BLOCKS, 256>>>(geo, app, con, out,
                                              W2c, b2c, W2r, b2r, W2l, b2l);
}

// round 12
// speedup vs baseline: 1.1975x; 1.0355x over previous
#include <cuda_runtime.h>
#include <math.h>
#include <stdint.h>

#define BB 2
#define NN 160
#define HH 256
#define C3 768
#define FF 512
#define NP (NN*NN)            // 25600
#define MM (BB*NN)            // 320
#define LOGIT_ELEMS (BB*NP*2) // 102400 per head
#define EMB_OFF (3*LOGIT_ELEMS)

// PQ scratch: [h = t*2+s][m][f]
__device__ float g_PQ[3 * 2 * MM * FF];

#define FFMA2(acc, a, b) asm("fma.rn.f32x2 %0, %1, %2, %0;" : "+l"(acc) : "l"(a), "l"(b))
#define PACKDUP(d, x)    asm("mov.b64 %0, {%1, %1};" : "=l"(d) : "r"(__float_as_uint(x)))
#define UNPK(lo, hi, v)  asm("mov.b64 {%0, %1}, %2;" : "=r"(lo), "=r"(hi) : "l"(v))
#define CPA16(dst, src)  asm volatile("cp.async.ca.shared.global [%0], [%1], 16;" :: "r"(dst), "l"(src) : "memory")
#define CPCOMMIT()       asm volatile("cp.async.commit_group;" ::: "memory")

#define BM 64
#define BN 64
#define BK 16
#define NK 48
#define GEMM_BLOCKS 240
#define JT 10
#define WRA_BLOCKS 1000
#define WRB_BLOCKS 4120
#define LG_BLOCKS 150

#define SMEM_BYTES 33824   // writer 33800 / logits 33792 / gemm 32768 union

// ---------------- writer role: TMA bulk pipeline ----------------
// wb in [0, 5120): b = wb/2560, i = (wb%2560)/16, j0 = ((wb%2560)%16)*10
__device__ __forceinline__ void writer_role(
    int wb,
    const float* __restrict__ geo, const float* __restrict__ app, const float* __restrict__ con,
    float* __restrict__ out, int tid, char* sm)
{
    const int b  = wb / 2560;
    const int rem = wb % 2560;
    const int i  = rem / 16;
    const int j0 = (rem % 16) * JT;

    const uint32_t sbase = (uint32_t)__cvta_generic_to_shared(sm);
    const uint32_t mbar  = sbase + 11 * 3072;

    if (tid == 0) {
        asm volatile("mbarrier.init.shared.b64 [%0], 1;" :: "r"(mbar) : "memory");
    }
    __syncthreads();
    if (tid == 0) {
        asm volatile("mbarrier.arrive.expect_tx.shared.b64 _, [%0], %1;"
                     :: "r"(mbar), "r"(11u * 3072u) : "memory");
    }
    __syncthreads();

    if (tid < 33) {
        const int r = tid / 3, seg = tid - 3 * (tid / 3);
        const int n = (r < JT) ? (j0 + r) : i;
        const float* src = ((seg == 0) ? geo : (seg == 1) ? app : con)
                           + ((size_t)b * NN + n) * HH;
        asm volatile(
            "cp.async.bulk.shared::cluster.global.mbarrier::complete_tx::bytes "
            "[%0], [%1], %2, [%3];"
            :: "r"(sbase + (uint32_t)(r * 3072 + seg * 1024)), "l"(src),
               "r"(1024u), "r"(mbar) : "memory");
    }

    if (tid < 2 * JT) {
        asm volatile(
            "{\n\t.reg .pred P;\n"
            "W%=:\n\t"
            "mbarrier.try_wait.parity.shared.b64 P, [%0], 0, 0x989680;\n\t"
            "@!P bra W%=;\n\t}"
            :: "r"(mbar) : "memory");

        const int jj = tid >> 1, half = tid & 1;
        const size_t pidx = (size_t)b * NP + (size_t)i * NN + (j0 + jj);
        float* dst = out + EMB_OFF + pidx * 1536 + half * 768;
        const uint32_t src = sbase + (uint32_t)((half ? JT : jj) * 3072);
        asm volatile(
            "cp.async.bulk.global.shared::cta.bulk_group [%0], [%1], %2;"
            :: "l"(dst), "r"(src), "r"(3072u) : "memory");
        asm volatile("cp.async.bulk.commit_group;" ::: "memory");
        asm volatile("cp.async.bulk.wait_group 0;" ::: "memory");
    }
    __syncthreads();
}

// ---------------- Kernel 1: latency-hardened GEMM + writer (1000 tiles) ----------------
__global__ __launch_bounds__(256) void k1_gemm_wr(
    const float* __restrict__ geo, const float* __restrict__ app, const float* __restrict__ con,
    const float* __restrict__ W1c, const float* __restrict__ b1c,
    const float* __restrict__ W1r, const float* __restrict__ b1r,
    const float* __restrict__ W1l, const float* __restrict__ b1l,
    float* __restrict__ out)
{
    __shared__ __align__(128) char sm[SMEM_BYTES];
    const int g = blockIdx.x;
    const int tid = threadIdx.x;

    if (g < GEMM_BLOCKS) {
        // smem: As[4][64x16] (4KB/stage), Bs[4][16x64] (4KB/stage)
        float (*As)[BM*BK] = (float(*)[BM*BK])sm;
        float (*Bs)[BK*BN] = (float(*)[BK*BN])(sm + 4 * 4096);
        const uint32_t sb = (uint32_t)__cvta_generic_to_shared(sm);
        const uint32_t aD = sb + tid * 16;
        const uint32_t bD = sb + 4 * 4096 + tid * 16;

        const int nt = g % 48;
        const int mt = g / 48;
        const int t  = nt >> 4;
        const int s  = (nt >> 3) & 1;
        const int f0 = (nt & 7) * BN;
        const float* W1 = (t==0 ? W1c : (t==1 ? W1r : W1l)) + (size_t)s * C3 * FF;
        const float* b1 = (t==0 ? b1c : (t==1 ? b1r : b1l));
        const int m0 = mt * BM;

        const int arow = tid >> 2, acol = (tid & 3) * 4;   // A cp.async: [row][16f] rows
        const int brow = tid >> 4, bcol = (tid & 15) * 4;  // B cp.async: [k][64f] rows
        const int rg = tid >> 4, cg = tid & 15;            // compute: 4m x 4n

        unsigned long long acc2[4][2];
        #pragma unroll
        for (int a = 0; a < 4; a++) { acc2[a][0] = 0ull; acc2[a][1] = 0ull; }

        // prologue: stages 0..2
        #pragma unroll
        for (int st = 0; st < 3; st++) {
            const int c0 = st * BK;
            const float* segp = geo;  // c0 < 256 for st<3 always (c0<=32)
            CPA16(aD + st * 4096, segp + (size_t)(m0 + arow) * HH + c0 + acol);
            CPA16(bD + st * 4096, W1 + (size_t)(c0 + brow) * FF + f0 + bcol);
            CPCOMMIT();
        }

        for (int kt = 0; kt < NK; kt++) {
            if (kt + 2 >= NK) {
                asm volatile("cp.async.wait_group 0;" ::: "memory");
            } else {
                asm volatile("cp.async.wait_group 2;" ::: "memory");
            }
            __syncthreads();

            const int cur = kt & 3;
            const float* Ab = As[cur];
            const float* Bb = Bs[cur];
            #pragma unroll
            for (int kg = 0; kg < 4; kg++) {
                float4 am[4];
                #pragma unroll
                for (int a = 0; a < 4; a++)
                    am[a] = *(const float4*)&Ab[(rg*4 + a) * BK + kg * 4];
                #pragma unroll
                for (int kk = 0; kk < 4; kk++) {
                    const ulonglong2 bv =
                        *(const ulonglong2*)&Bb[(kg*4 + kk) * BN + cg * 4];
                    #pragma unroll
                    for (int a = 0; a < 4; a++) {
                        const float av = ((const float*)&am[a])[kk];
                        unsigned long long ad;
                        PACKDUP(ad, av);
                        FFMA2(acc2[a][0], ad, bv.x);
                        FFMA2(acc2[a][1], ad, bv.y);
                    }
                }
            }

            if (kt + 3 < NK) {
                const int st = (kt + 3) & 3;
                const int c0 = (kt + 3) * BK;
                const float* segp = (c0 < 256) ? geo : ((c0 < 512) ? app : con);
                CPA16(aD + st * 4096, segp + (size_t)(m0 + arow) * HH + (c0 & 255) + acol);
                CPA16(bD + st * 4096, W1 + (size_t)(c0 + brow) * FF + f0 + bcol);
                CPCOMMIT();
            }
        }

        float bv4[4] = {0.f, 0.f, 0.f, 0.f};
        if (s == 1) {
            const float4 tb = *(const float4*)(b1 + f0 + cg*4);
            bv4[0]=tb.x; bv4[1]=tb.y; bv4[2]=tb.z; bv4[3]=tb.w;
        }
        const size_t hb = (size_t)(t*2 + s) * MM * FF;
        #pragma unroll
        for (int a = 0; a < 4; a++) {
            const int m = m0 + rg*4 + a;
            unsigned int lo0, hi0, lo1, hi1;
            UNPK(lo0, hi0, acc2[a][0]);
            UNPK(lo1, hi1, acc2[a][1]);
            *(float4*)(g_PQ + hb + (size_t)m * FF + f0 + cg*4) =
                make_float4(__uint_as_float(lo0) + bv4[0], __uint_as_float(hi0) + bv4[1],
                            __uint_as_float(lo1) + bv4[2], __uint_as_float(hi1) + bv4[3]);
        }
    } else {
        writer_role(g - GEMM_BLOCKS, geo, app, con, out, tid, sm);
    }
}

// ---------------- Kernel 2: logits (32i x 32j, acc[4]) + writer (4120 tiles) ----------------
__global__ __launch_bounds__(256) void k2_lg_wr(
    const float* __restrict__ geo, const float* __restrict__ app, const float* __restrict__ con,
    float* __restrict__ out,
    const float* __restrict__ W2c, const float* __restrict__ b2c,
    const float* __restrict__ W2r, const float* __restrict__ b2r,
    const float* __restrict__ W2l, const float* __restrict__ b2l)
{
    __shared__ __align__(128) char sm[SMEM_BYTES];
    const int g = blockIdx.x;
    const int tid = threadIdx.x;

    if (g < LG_BLOCKS) {
        float* sP = (float*)sm;            // 32*132
        float* sQ = sP + 32*132;           // 32*128
        float* sW = sQ + 32*128;           // 128
        const int t = g / 50;
        const int r50 = g % 50;
        const int b = r50 / 25;
        const int r25 = r50 % 25;
        const int i0 = (r25 / 5) * 32;
        const int j0 = (r25 % 5) * 32;
        const float* W2 = (t==0 ? W2c : (t==1 ? W2r : W2l));
        const float* b2 = (t==0 ? b2c : (t==1 ? b2r : b2l));
        const size_t boff = (size_t)b * NN * FF;
        const float* Pb = g_PQ + (size_t)(t*2 + 0) * MM * FF + boff;
        const float* Qb = g_PQ + (size_t)(t*2 + 1) * MM * FF + boff;
        const int il = tid >> 5, jl = tid & 31;
        const int lr = tid >> 3, lv = tid & 7;

        float acc[4] = {0.f, 0.f, 0.f, 0.f};
        for (int fc = 0; fc < 4; fc++) {
            const int f0 = fc * 128;
            {
                const size_t ro = (size_t)(j0 + lr) * FF + f0;
                float* dp = sP + lr * 132;
                #pragma unroll
                for (int u = 0; u < 4; u++) {
                    const int fl = (lv + u * 8) * 4;
                    *(float4*)(dp + fl) = *(const float4*)(Pb + ro + fl);
                }
            }
            {
                const size_t ro = (size_t)(i0 + lr) * FF + f0;
                float* dp = sQ + lr * 128;
                #pragma unroll
                for (int u = 0; u < 4; u++) {
                    const int fl = (lv + u * 8) * 4;
                    *(float4*)(dp + fl) = *(const float4*)(Qb + ro + fl);
                }
            }
            if (tid < 128) {
                const float2 w2v = ((const float2*)W2)[f0 + tid];
                sW[tid] = w2v.x - w2v.y;
            }
            __syncthreads();

            const float* pr = sP + jl * 132;
            const float* q0 = sQ + (il * 4) * 128;
            #pragma unroll 4
            for (int f = 0; f < 128; f += 4) {
                const float4 p = *(const float4*)(pr + f);
                const float4 w = *(const float4*)(sW + f);
                #pragma unroll
                for (int a = 0; a < 4; a++) {
                    const float4 q = *(const float4*)(q0 + a * 128 + f);
                    acc[a] = fmaf(fmaxf(p.x + q.x, 0.f), w.x, acc[a]);
                    acc[a] = fmaf(fmaxf(p.y + q.y, 0.f), w.y, acc[a]);
                    acc[a] = fmaf(fmaxf(p.z + q.z, 0.f), w.z, acc[a]);
                    acc[a] = fmaf(fmaxf(p.w + q.w, 0.f), w.w, acc[a]);
                }
            }
            __syncthreads();
        }

        const float bd = b2[0] - b2[1];
        float2* o = (float2*)(out + (size_t)t * LOGIT_ELEMS) + (size_t)b * NP;
        const int j = j0 + jl;
        #pragma unroll
        for (int a = 0; a < 4; a++) {
            const float d = acc[a] + bd;
            const float p0 = 1.0f / (1.0f + __expf(-d));
            o[(size_t)(i0 + il*4 + a) * NN + j] = make_float2(p0, 1.0f - p0);
        }
    } else {
        writer_role(WRA_BLOCKS + (g - LG_BLOCKS), geo, app, con, out, tid, sm);
    }
}

extern "C" void kernel_launch(void* const* d_in, const int* in_sizes, int n_in,
                              void* d_out, int out_size) {
    const float* geo = (const float*)d_in[0];
    const float* app = (const float*)d_in[1];
    const float* con = (const float*)d_in[2];
    const float* W1c = (const float*)d_in[3];
    const float* b1c = (const float*)d_in[4];
    const float* W2c = (const float*)d_in[5];
    const float* b2c = (const float*)d_in[6];
    const float* W1r = (const float*)d_in[7];
    const float* b1r = (const float*)d_in[8];
    const float* W2r = (const float*)d_in[9];
    const float* b2r = (const float*)d_in[10];
    const float* W1l = (const float*)d_in[11];
    const float* b1l = (const float*)d_in[12];
    const float* W2l = (const float*)d_in[13];
    const float* b2l = (const float*)d_in[14];
    float* out = (float*)d_out;

    k1_gemm_wr<<<GEMM_BLOCKS + WRA_BLOCKS, 256>>>(geo, app, con,
                                                  W1c, b1c, W1r, b1r, W1l, b1l, out);
    k2_lg_wr<<<LG_BLOCKS + WRB_BLOCKS, 256>>>(geo, app, con, out,
                                              W2c, b2c, W2r, b2r, W2l, b2l);
}